// round 14
// baseline (speedup 1.0000x reference)
#include <cuda_runtime.h>
#include <cuda_bf16.h>
#include <cstdint>

// Problem constants
#define MAXN 100000
#define MAXE 600000
#define D 128
#define L_LAYERS 5
#define NPART 296
#define SCAN_BLK 1024

// ---------------- scratch (device globals; no allocation allowed) -------------
__device__ float g_bufA[MAXN * D];
// aggregated z in split-bf16 (padded by 128 rows so tail-tile cp.async stays in-bounds)
__device__ __align__(16) __nv_bfloat16 g_zhi[(MAXN + 128) * D];
__device__ __align__(16) __nv_bfloat16 g_zlo[(MAXN + 128) * D];
__device__ int   g_deg[MAXN];
__device__ int   g_rowptr[MAXN + 1];
__device__ int   g_cursor[MAXN];
__device__ int   g_col[MAXE];
__device__ float g_part[NPART * D];
__device__ int   g_bsum[128];
__device__ int   g_boff[128];
// pre-split transposed weights: 10 matrices x 128x128 bf16 (as uint4)
__device__ uint4 g_WhiT[10 * 128 * 128 / 8];
__device__ uint4 g_WloT[10 * 128 * 128 / 8];

// ---------------- utility kernels --------------------------------------------
__global__ void k_zero_int(int* __restrict__ p, int n) {
    int i = blockIdx.x * blockDim.x + threadIdx.x;
    if (i < n) p[i] = 0;
}

__global__ void k_gather(const int* __restrict__ x, const float* __restrict__ emb,
                         float* __restrict__ h, int n) {
    int i = blockIdx.x * blockDim.x + threadIdx.x;
    if (i < n * (D / 4)) {
        int node = i >> 5;
        int q    = i & 31;
        reinterpret_cast<float4*>(h)[(size_t)node * 32 + q] =
            reinterpret_cast<const float4*>(emb)[(size_t)x[node] * 32 + q];
    }
}

__global__ void k_count(const int* __restrict__ dst, int* __restrict__ deg, int e) {
    int i = blockIdx.x * blockDim.x + threadIdx.x;
    if (i < e) atomicAdd(&deg[dst[i]], 1);
}

// split + transpose weights: WT[n][k] = split(W[k][n]); 40 blocks (mat, k-quarter)
__global__ void k_wsplit(const float* __restrict__ Wa, const float* __restrict__ Wb,
                         __nv_bfloat16* __restrict__ hi, __nv_bfloat16* __restrict__ lo) {
    int mat = blockIdx.x >> 2, kq = blockIdx.x & 3;
    const float* W = (mat < 5) ? (Wa + mat * 16384) : (Wb + (mat - 5) * 16384);
    __nv_bfloat16* H  = hi + mat * 16384;
    __nv_bfloat16* Lo = lo + mat * 16384;
    int nidx = threadIdx.x;
    for (int k = kq * 32; k < kq * 32 + 32; k++) {
        float x = W[k * 128 + nidx];
        __nv_bfloat16 h = __float2bfloat16(x);
        H[nidx * 128 + k]  = h;
        Lo[nidx * 128 + k] = __float2bfloat16(x - __bfloat162float(h));
    }
}

// ---- 3-phase scan -------------------------------------------------------------
__global__ void k_scan_blk(const int* __restrict__ deg, int* __restrict__ rowptr,
                           int* __restrict__ bsum, int n) {
    int i = blockIdx.x * SCAN_BLK + threadIdx.x;
    int lane = threadIdx.x & 31, wid = threadIdx.x >> 5;
    int v = (i < n) ? deg[i] : 0;
    int inc = v;
#pragma unroll
    for (int o = 1; o < 32; o <<= 1) {
        int t = __shfl_up_sync(0xFFFFFFFFu, inc, o);
        if (lane >= o) inc += t;
    }
    __shared__ int wsum[32];
    if (lane == 31) wsum[wid] = inc;
    __syncthreads();
    if (wid == 0) {
        int s = wsum[lane];
#pragma unroll
        for (int o = 1; o < 32; o <<= 1) {
            int t = __shfl_up_sync(0xFFFFFFFFu, s, o);
            if (lane >= o) s += t;
        }
        wsum[lane] = s;
    }
    __syncthreads();
    int base = (wid > 0) ? wsum[wid - 1] : 0;
    if (i < n) rowptr[i] = base + inc - v;
    if (threadIdx.x == SCAN_BLK - 1) bsum[blockIdx.x] = base + inc;
}

__global__ void k_scan_top(const int* __restrict__ bsum, int* __restrict__ boff,
                           int* __restrict__ total_out, int nb) {
    int t = threadIdx.x, lane = t & 31, wid = t >> 5;
    int v = (t < nb) ? bsum[t] : 0;
    int inc = v;
#pragma unroll
    for (int o = 1; o < 32; o <<= 1) {
        int u = __shfl_up_sync(0xFFFFFFFFu, inc, o);
        if (lane >= o) inc += u;
    }
    __shared__ int ws[32];
    __shared__ int wsx[33];
    if (lane == 31) ws[wid] = inc;
    __syncthreads();
    if (t == 0) {
        wsx[0] = 0;
        for (int w = 0; w < 4; w++) wsx[w + 1] = wsx[w] + ws[w];
    }
    __syncthreads();
    int excl = wsx[wid] + inc - v;
    if (t < nb) boff[t] = excl;
    if (t == blockDim.x - 1) *total_out = wsx[4];
}

__global__ void k_scan_add(int* __restrict__ rowptr, int* __restrict__ cursor,
                           const int* __restrict__ boff, int n) {
    int i = blockIdx.x * blockDim.x + threadIdx.x;
    if (i < n) {
        int r = rowptr[i] + boff[i >> 10];
        rowptr[i] = r;
        cursor[i] = r;
    }
}

__global__ void k_scatter(const int* __restrict__ src, const int* __restrict__ dst,
                          int* __restrict__ cursor, int* __restrict__ col, int e) {
    int i = blockIdx.x * blockDim.x + threadIdx.x;
    if (i < e) {
        int d = dst[i];
        int p = atomicAdd(&cursor[d], 1);
        col[p] = src[i];
    }
}

__device__ __forceinline__ uint32_t pack_bf16x2(float a, float b) {
    __nv_bfloat162 t = __floats2bfloat162_rn(a, b);
    return *reinterpret_cast<uint32_t*>(&t);
}

// z = h + sum neighbors, emitted directly as split-bf16 hi/lo.
// 8 nodes per 256-thread block; unroll-4 for MLP=4 on the gather chain.
__global__ void k_agg(const float* __restrict__ h, const int* __restrict__ rowptr,
                      const int* __restrict__ col,
                      __nv_bfloat16* __restrict__ zhi, __nv_bfloat16* __restrict__ zlo,
                      int n) {
    int node = blockIdx.x * 8 + (threadIdx.x >> 5);
    if (node >= n) return;
    int lane = threadIdx.x & 31;
    const float4* h4 = reinterpret_cast<const float4*>(h);
    float4 acc = h4[(size_t)node * 32 + lane];
    int s0 = rowptr[node], s1 = rowptr[node + 1];
    int j = s0;
    for (; j + 3 < s1; j += 4) {
        int c0 = __ldg(&col[j]),     c1 = __ldg(&col[j + 1]);
        int c2 = __ldg(&col[j + 2]), c3 = __ldg(&col[j + 3]);
        float4 v0 = __ldg(&h4[(size_t)c0 * 32 + lane]);
        float4 v1 = __ldg(&h4[(size_t)c1 * 32 + lane]);
        float4 v2 = __ldg(&h4[(size_t)c2 * 32 + lane]);
        float4 v3 = __ldg(&h4[(size_t)c3 * 32 + lane]);
        acc.x += (v0.x + v1.x) + (v2.x + v3.x);
        acc.y += (v0.y + v1.y) + (v2.y + v3.y);
        acc.z += (v0.z + v1.z) + (v2.z + v3.z);
        acc.w += (v0.w + v1.w) + (v2.w + v3.w);
    }
    for (; j < s1; j++) {
        int c = __ldg(&col[j]);
        float4 v = __ldg(&h4[(size_t)c * 32 + lane]);
        acc.x += v.x; acc.y += v.y; acc.z += v.z; acc.w += v.w;
    }
    uint2 hp, lp;
    hp.x = pack_bf16x2(acc.x, acc.y);
    hp.y = pack_bf16x2(acc.z, acc.w);
    float hx = __bfloat162float(__float2bfloat16(acc.x));
    float hy = __bfloat162float(__float2bfloat16(acc.y));
    float hz = __bfloat162float(__float2bfloat16(acc.z));
    float hw = __bfloat162float(__float2bfloat16(acc.w));
    lp.x = pack_bf16x2(acc.x - hx, acc.y - hy);
    lp.y = pack_bf16x2(acc.z - hz, acc.w - hw);
    reinterpret_cast<uint2*>(zhi)[(size_t)node * 32 + lane] = hp;
    reinterpret_cast<uint2*>(zlo)[(size_t)node * 32 + lane] = lp;
}

// ---------------- fused 2-GEMM layer: h = relu(relu(z@Wa+ba)@Wb+bb) -----------
// Block tile 128 rows x 128 cols; 8 warps (4m x 2n), warp tile 32x64; K=128.
// Z pre-split (bf16 hi/lo); staging pipelined in 4 k-chunk cp.async groups.
#define TSTR   272
#define SM_ZHI 0
#define SM_ZLO (128 * TSTR)                  // 34816
#define SM_WAHI (2 * 128 * TSTR)             // 69632
#define SM_WALO (SM_WAHI + 128 * TSTR)       // 104448
#define SM_WBHI (SM_WALO + 128 * TSTR)       // 139264
#define SM_WBLO (SM_WBHI + 128 * TSTR)       // 174080
#define SM_BA  (SM_WBLO + 128 * TSTR)        // 208896
#define SM_BB  (SM_BA + 512)                 // 209408
#define SMEM_L (SM_BB + 512)                 // 209920

__device__ __forceinline__ uint32_t smem_u32(const void* p) {
    uint32_t a;
    asm("{ .reg .u64 t; cvta.to.shared.u64 t, %1; cvt.u32.u64 %0, t; }" : "=r"(a) : "l"(p));
    return a;
}
__device__ __forceinline__ void ldsm_x4(uint32_t* r, uint32_t addr) {
    asm volatile("ldmatrix.sync.aligned.m8n8.x4.shared.b16 {%0,%1,%2,%3}, [%4];"
        : "=r"(r[0]), "=r"(r[1]), "=r"(r[2]), "=r"(r[3]) : "r"(addr));
}
__device__ __forceinline__ void mma_16816(float* c, const uint32_t* a, const uint32_t* b) {
    asm volatile(
        "mma.sync.aligned.m16n8k16.row.col.f32.bf16.bf16.f32 "
        "{%0,%1,%2,%3}, {%4,%5,%6,%7}, {%8,%9}, {%0,%1,%2,%3};"
        : "+f"(c[0]), "+f"(c[1]), "+f"(c[2]), "+f"(c[3])
        : "r"(a[0]), "r"(a[1]), "r"(a[2]), "r"(a[3]), "r"(b[0]), "r"(b[1]));
}
__device__ __forceinline__ void cp_async16(uint32_t saddr, const void* gptr) {
    asm volatile("cp.async.ca.shared.global [%0], [%1], 16;" :: "r"(saddr), "l"(gptr));
}

// One GEMM pass. If PIPE, wait on the staged k-chunk groups as compute advances:
// commit order is G0..G3 (Z+Wa k-chunks of 2 k-steps) then G4 (Wb).
template <int PIPE>
__device__ __forceinline__ void gemm_pass(uint32_t sb, uint32_t whi_ofs, uint32_t wlo_ofs,
                                          int lane, int m0, int n0, float acc[2][8][4]) {
#pragma unroll
    for (int a = 0; a < 2; a++)
#pragma unroll
        for (int b = 0; b < 8; b++)
#pragma unroll
            for (int c = 0; c < 4; c++) acc[a][b][c] = 0.f;

    const uint32_t a_row  = m0 + (lane & 15);
    const uint32_t a_coff = (lane >> 4) * 8;
    const uint32_t b_row  = n0 + ((lane >> 4) << 3) + (lane & 7);
    const uint32_t b_coff = ((lane >> 3) & 1) * 8;

#pragma unroll
    for (int ks = 0; ks < 8; ks++) {
        if (PIPE) {
            if (ks == 0) { asm volatile("cp.async.wait_group 4;" ::: "memory"); __syncthreads(); }
            if (ks == 2) { asm volatile("cp.async.wait_group 3;" ::: "memory"); __syncthreads(); }
            if (ks == 4) { asm volatile("cp.async.wait_group 2;" ::: "memory"); __syncthreads(); }
            if (ks == 6) { asm volatile("cp.async.wait_group 1;" ::: "memory"); __syncthreads(); }
        }
        const int k = ks * 16;
        uint32_t ah[2][4], al[2][4];
#pragma unroll
        for (int mf = 0; mf < 2; mf++) {
            uint32_t addr = sb + SM_ZHI + (a_row + mf * 16) * TSTR + (k + a_coff) * 2;
            ldsm_x4(ah[mf], addr);
            ldsm_x4(al[mf], addr + (SM_ZLO - SM_ZHI));
        }
#pragma unroll
        for (int nfg = 0; nfg < 4; nfg++) {
            uint32_t baddr = sb + whi_ofs + (b_row + nfg * 16) * TSTR + (k + b_coff) * 2;
            uint32_t bh[4], bl[4];
            ldsm_x4(bh, baddr);
            ldsm_x4(bl, baddr + (wlo_ofs - whi_ofs));
#pragma unroll
            for (int mf = 0; mf < 2; mf++) {
                mma_16816(acc[mf][nfg * 2 + 0], ah[mf], bh + 0);
                mma_16816(acc[mf][nfg * 2 + 0], al[mf], bh + 0);
                mma_16816(acc[mf][nfg * 2 + 0], ah[mf], bl + 0);
                mma_16816(acc[mf][nfg * 2 + 1], ah[mf], bh + 2);
                mma_16816(acc[mf][nfg * 2 + 1], al[mf], bh + 2);
                mma_16816(acc[mf][nfg * 2 + 1], ah[mf], bl + 2);
            }
        }
    }
}

__global__ __launch_bounds__(256, 1)
void k_layer(const uint4* __restrict__ Zhi, const uint4* __restrict__ Zlo,
             const uint4* __restrict__ WaHi, const uint4* __restrict__ WaLo,
             const uint4* __restrict__ WbHi, const uint4* __restrict__ WbLo,
             const float* __restrict__ ba, const float* __restrict__ bb,
             float* __restrict__ C, int n) {
    extern __shared__ char sm[];
    const uint32_t sb = smem_u32(sm);
    const int tid = threadIdx.x;
    const int lane = tid & 31, w = tid >> 5;
    const int rowBase = blockIdx.x * 128;

    // ---- pipelined staging: 4 groups of (Z + Wa) k-chunks, then Wb ----
    // thread = (row = tid>>1, c2 = tid&1); per group each thread moves
    // 2 chunks x {Zhi, Zlo, WaHi, WaLo} covering cols 32g..32g+31.
    {
        const int row = tid >> 1, c2 = tid & 1;
        const size_t zrow = (size_t)(rowBase + row) * 16;
#pragma unroll
        for (int g = 0; g < 4; g++) {
#pragma unroll
            for (int i = 0; i < 2; i++) {
                int ch = g * 4 + c2 * 2 + i;                    // uint4 index in row
                uint32_t dofs = row * TSTR + ch * 16;
                cp_async16(sb + SM_ZHI + dofs, Zhi + zrow + ch);
                cp_async16(sb + SM_ZLO + dofs, Zlo + zrow + ch);
                cp_async16(sb + SM_WAHI + dofs, WaHi + row * 16 + ch);
                cp_async16(sb + SM_WALO + dofs, WaLo + row * 16 + ch);
            }
            asm volatile("cp.async.commit_group;" ::: "memory");
        }
#pragma unroll
        for (int it = 0; it < 8; it++) {
            int j = tid + it * 256;
            int r2 = j >> 4, chunk = j & 15;
            uint32_t dofs = r2 * TSTR + chunk * 16;
            cp_async16(sb + SM_WBHI + dofs, WbHi + r2 * 16 + chunk);
            cp_async16(sb + SM_WBLO + dofs, WbLo + r2 * 16 + chunk);
        }
        asm volatile("cp.async.commit_group;" ::: "memory");
    }

    if (tid < 128) {
        reinterpret_cast<float*>(sm + SM_BA)[tid] = ba[tid];
        reinterpret_cast<float*>(sm + SM_BB)[tid] = bb[tid];
    }

    const int m0 = (w >> 1) * 32, n0 = (w & 1) * 64;
    float acc[2][8][4];

    // ---- phase 1: acc1 = Z @ Wa (pipelined waits inside) ----
    gemm_pass<1>(sb, SM_WAHI, SM_WALO, lane, m0, n0, acc);
    __syncthreads();                                       // all ldsm of Z done

    // ---- relu(acc1+ba) -> Z smem (bf16 hi/lo), each warp its own quadrant ----
    {
        const float* bav = reinterpret_cast<const float*>(sm + SM_BA);
#pragma unroll
        for (int mf = 0; mf < 2; mf++) {
#pragma unroll
            for (int nf = 0; nf < 8; nf++) {
                int r = m0 + mf * 16 + (lane >> 2);
                int c = n0 + nf * 8 + (lane & 3) * 2;
                float b0 = bav[c], b1 = bav[c + 1];
                float z0 = fmaxf(acc[mf][nf][0] + b0, 0.f);
                float z1 = fmaxf(acc[mf][nf][1] + b1, 0.f);
                float z2 = fmaxf(acc[mf][nf][2] + b0, 0.f);
                float z3 = fmaxf(acc[mf][nf][3] + b1, 0.f);
                float h0 = __bfloat162float(__float2bfloat16(z0));
                float h1 = __bfloat162float(__float2bfloat16(z1));
                float h2 = __bfloat162float(__float2bfloat16(z2));
                float h3 = __bfloat162float(__float2bfloat16(z3));
                *reinterpret_cast<uint32_t*>(sm + SM_ZHI + r * TSTR + c * 2) =
                    pack_bf16x2(z0, z1);
                *reinterpret_cast<uint32_t*>(sm + SM_ZLO + r * TSTR + c * 2) =
                    pack_bf16x2(z0 - h0, z1 - h1);
                *reinterpret_cast<uint32_t*>(sm + SM_ZHI + (r + 8) * TSTR + c * 2) =
                    pack_bf16x2(z2, z3);
                *reinterpret_cast<uint32_t*>(sm + SM_ZLO + (r + 8) * TSTR + c * 2) =
                    pack_bf16x2(z2 - h2, z3 - h3);
            }
        }
    }
    asm volatile("cp.async.wait_group 0;" ::: "memory");   // Wb resident
    __syncthreads();

    // ---- phase 2: acc2 = Z' @ Wb ----
    gemm_pass<0>(sb, SM_WBHI, SM_WBLO, lane, m0, n0, acc);

    // ---- epilogue: relu(acc2+bb) -> global fp32 ----
    {
        const float* bbv = reinterpret_cast<const float*>(sm + SM_BB);
#pragma unroll
        for (int mf = 0; mf < 2; mf++) {
#pragma unroll
            for (int nf = 0; nf < 8; nf++) {
                int r = m0 + mf * 16 + (lane >> 2);
                int c = n0 + nf * 8 + (lane & 3) * 2;
                float b0 = bbv[c], b1 = bbv[c + 1];
                int gr0 = rowBase + r;
                if (gr0 < n) {
                    float2 v;
                    v.x = fmaxf(acc[mf][nf][0] + b0, 0.f);
                    v.y = fmaxf(acc[mf][nf][1] + b1, 0.f);
                    *reinterpret_cast<float2*>(C + (size_t)gr0 * 128 + c) = v;
                }
                int gr1 = gr0 + 8;
                if (gr1 < n) {
                    float2 v;
                    v.x = fmaxf(acc[mf][nf][2] + b0, 0.f);
                    v.y = fmaxf(acc[mf][nf][3] + b1, 0.f);
                    *reinterpret_cast<float2*>(C + (size_t)gr1 * 128 + c) = v;
                }
            }
        }
    }
}

// ---------------- pool + final -------------------------------------------------
__global__ void k_pool_partial(const float* __restrict__ h, float* __restrict__ part, int n) {
    int d = threadIdx.x;
    float acc = 0.f;
    for (int r = blockIdx.x; r < n; r += gridDim.x)
        acc += h[(size_t)r * D + d];
    part[blockIdx.x * D + d] = acc;
}

__global__ void k_final(const float* __restrict__ part, const float* __restrict__ Wlin,
                        const float* __restrict__ blin, float* __restrict__ out) {
    __shared__ float pooled[D];
    int t = threadIdx.x;
    float acc = 0.f;
    for (int p = 0; p < NPART; p++) acc += part[p * D + t];
    pooled[t] = acc;
    __syncthreads();
    float o = blin[t];
    for (int d = 0; d < D; d++) o = fmaf(pooled[d], Wlin[d * D + t], o);
    out[t] = o;
}

// ---------------- launch -------------------------------------------------------
extern "C" void kernel_launch(void* const* d_in, const int* in_sizes, int n_in,
                              void* d_out, int out_size) {
    const int*   x    = (const int*)d_in[0];
    const int*   ei   = (const int*)d_in[1];
    const float* emb  = (const float*)d_in[2];
    const float* Wa   = (const float*)d_in[3];
    const float* ba   = (const float*)d_in[4];
    const float* Wb   = (const float*)d_in[5];
    const float* bb   = (const float*)d_in[6];
    const float* Wlin = (const float*)d_in[7];
    const float* blin = (const float*)d_in[8];
    float* out = (float*)d_out;

    const int N = in_sizes[0];
    const int E = in_sizes[1] / 2;
    const int* src = ei;
    const int* dst = ei + E;

    float *A, *part;
    __nv_bfloat16 *zhi, *zlo;
    int *deg, *rowptr, *cursor, *col, *bsum, *boff;
    uint4 *whi, *wlo;
    cudaGetSymbolAddress((void**)&A, g_bufA);
    cudaGetSymbolAddress((void**)&zhi, g_zhi);
    cudaGetSymbolAddress((void**)&zlo, g_zlo);
    cudaGetSymbolAddress((void**)&deg, g_deg);
    cudaGetSymbolAddress((void**)&rowptr, g_rowptr);
    cudaGetSymbolAddress((void**)&cursor, g_cursor);
    cudaGetSymbolAddress((void**)&col, g_col);
    cudaGetSymbolAddress((void**)&part, g_part);
    cudaGetSymbolAddress((void**)&bsum, g_bsum);
    cudaGetSymbolAddress((void**)&boff, g_boff);
    cudaGetSymbolAddress((void**)&whi, g_WhiT);
    cudaGetSymbolAddress((void**)&wlo, g_WloT);

    cudaFuncSetAttribute(k_layer, cudaFuncAttributeMaxDynamicSharedMemorySize, SMEM_L);

    // h = emb[x]
    k_gather<<<(N * 32 + 255) / 256, 256>>>(x, emb, A, N);

    // pre-split weights to transposed bf16 hi/lo
    k_wsplit<<<40, 128>>>(Wa, Wb, (__nv_bfloat16*)whi, (__nv_bfloat16*)wlo);

    // CSR build
    k_zero_int<<<(N + 255) / 256, 256>>>(deg, N);
    k_count<<<(E + 255) / 256, 256>>>(dst, deg, E);
    const int nb = (N + SCAN_BLK - 1) / SCAN_BLK;
    k_scan_blk<<<nb, SCAN_BLK>>>(deg, rowptr, bsum, N);
    k_scan_top<<<1, 128>>>(bsum, boff, rowptr + N, nb);
    k_scan_add<<<(N + 255) / 256, 256>>>(rowptr, cursor, boff, N);
    k_scatter<<<(E + 255) / 256, 256>>>(src, dst, cursor, col, E);

    const int layer_blocks = (N + 127) / 128;
    const int agg_blocks   = (N + 7) / 8;
    for (int l = 0; l < L_LAYERS; l++) {
        // z = h + agg(h), emitted as split-bf16
        k_agg<<<agg_blocks, 256>>>(A, rowptr, col, zhi, zlo, N);
        // h = relu(relu(z@Wa+ba)@Wb+bb)
        k_layer<<<layer_blocks, 256, SMEM_L>>>(
            (const uint4*)zhi, (const uint4*)zlo,
            whi + (size_t)l * 2048, wlo + (size_t)l * 2048,
            whi + (size_t)(5 + l) * 2048, wlo + (size_t)(5 + l) * 2048,
            ba + l * D, bb + l * D, A, N);
    }

    k_pool_partial<<<NPART, 128>>>(A, part, N);
    k_final<<<1, 128>>>(part, Wlin, blin, out);
}

// round 15
// speedup vs baseline: 1.1048x; 1.1048x over previous
#include <cuda_runtime.h>
#include <cuda_bf16.h>
#include <cstdint>

// Problem constants
#define MAXN 100000
#define MAXE 600000
#define D 128
#define L_LAYERS 5
#define NPART 296
#define SCAN_BLK 1024

// ---------------- scratch (device globals; no allocation allowed) -------------
__device__ float g_bufA[MAXN * D];
// aggregated z in split-bf16 (padded by 128 rows so tail-tile cp.async stays in-bounds)
__device__ __align__(16) __nv_bfloat16 g_zhi[(MAXN + 128) * D];
__device__ __align__(16) __nv_bfloat16 g_zlo[(MAXN + 128) * D];
__device__ int   g_deg[MAXN];
__device__ int   g_rowptr[MAXN + 1];
__device__ int   g_cursor[MAXN];
__device__ int   g_col[MAXE];
__device__ float g_part[NPART * D];
__device__ int   g_bsum[128];
__device__ int   g_boff[128];
// pre-split transposed weights: 10 matrices x 128x128 bf16 (as uint4)
__device__ uint4 g_WhiT[10 * 128 * 128 / 8];
__device__ uint4 g_WloT[10 * 128 * 128 / 8];

// ---------------- utility kernels --------------------------------------------
__global__ void k_zero_int(int* __restrict__ p, int n) {
    int i = blockIdx.x * blockDim.x + threadIdx.x;
    if (i < n) p[i] = 0;
}

__global__ void k_gather(const int* __restrict__ x, const float* __restrict__ emb,
                         float* __restrict__ h, int n) {
    int i = blockIdx.x * blockDim.x + threadIdx.x;
    if (i < n * (D / 4)) {
        int node = i >> 5;
        int q    = i & 31;
        reinterpret_cast<float4*>(h)[(size_t)node * 32 + q] =
            reinterpret_cast<const float4*>(emb)[(size_t)x[node] * 32 + q];
    }
}

__global__ void k_count(const int* __restrict__ dst, int* __restrict__ deg, int e) {
    int i = blockIdx.x * blockDim.x + threadIdx.x;
    if (i < e) atomicAdd(&deg[dst[i]], 1);
}

// split + transpose weights: WT[n][k] = split(W[k][n]); 40 blocks (mat, k-quarter)
__global__ void k_wsplit(const float* __restrict__ Wa, const float* __restrict__ Wb,
                         __nv_bfloat16* __restrict__ hi, __nv_bfloat16* __restrict__ lo) {
    int mat = blockIdx.x >> 2, kq = blockIdx.x & 3;
    const float* W = (mat < 5) ? (Wa + mat * 16384) : (Wb + (mat - 5) * 16384);
    __nv_bfloat16* H  = hi + mat * 16384;
    __nv_bfloat16* Lo = lo + mat * 16384;
    int nidx = threadIdx.x;
    for (int k = kq * 32; k < kq * 32 + 32; k++) {
        float x = W[k * 128 + nidx];
        __nv_bfloat16 h = __float2bfloat16(x);
        H[nidx * 128 + k]  = h;
        Lo[nidx * 128 + k] = __float2bfloat16(x - __bfloat162float(h));
    }
}

// ---- 3-phase scan -------------------------------------------------------------
__global__ void k_scan_blk(const int* __restrict__ deg, int* __restrict__ rowptr,
                           int* __restrict__ bsum, int n) {
    int i = blockIdx.x * SCAN_BLK + threadIdx.x;
    int lane = threadIdx.x & 31, wid = threadIdx.x >> 5;
    int v = (i < n) ? deg[i] : 0;
    int inc = v;
#pragma unroll
    for (int o = 1; o < 32; o <<= 1) {
        int t = __shfl_up_sync(0xFFFFFFFFu, inc, o);
        if (lane >= o) inc += t;
    }
    __shared__ int wsum[32];
    if (lane == 31) wsum[wid] = inc;
    __syncthreads();
    if (wid == 0) {
        int s = wsum[lane];
#pragma unroll
        for (int o = 1; o < 32; o <<= 1) {
            int t = __shfl_up_sync(0xFFFFFFFFu, s, o);
            if (lane >= o) s += t;
        }
        wsum[lane] = s;
    }
    __syncthreads();
    int base = (wid > 0) ? wsum[wid - 1] : 0;
    if (i < n) rowptr[i] = base + inc - v;
    if (threadIdx.x == SCAN_BLK - 1) bsum[blockIdx.x] = base + inc;
}

__global__ void k_scan_top(const int* __restrict__ bsum, int* __restrict__ boff,
                           int* __restrict__ total_out, int nb) {
    int t = threadIdx.x, lane = t & 31, wid = t >> 5;
    int v = (t < nb) ? bsum[t] : 0;
    int inc = v;
#pragma unroll
    for (int o = 1; o < 32; o <<= 1) {
        int u = __shfl_up_sync(0xFFFFFFFFu, inc, o);
        if (lane >= o) inc += u;
    }
    __shared__ int ws[32];
    __shared__ int wsx[33];
    if (lane == 31) ws[wid] = inc;
    __syncthreads();
    if (t == 0) {
        wsx[0] = 0;
        for (int w = 0; w < 4; w++) wsx[w + 1] = wsx[w] + ws[w];
    }
    __syncthreads();
    int excl = wsx[wid] + inc - v;
    if (t < nb) boff[t] = excl;
    if (t == blockDim.x - 1) *total_out = wsx[4];
}

__global__ void k_scan_add(int* __restrict__ rowptr, int* __restrict__ cursor,
                           const int* __restrict__ boff, int n) {
    int i = blockIdx.x * blockDim.x + threadIdx.x;
    if (i < n) {
        int r = rowptr[i] + boff[i >> 10];
        rowptr[i] = r;
        cursor[i] = r;
    }
}

__global__ void k_scatter(const int* __restrict__ src, const int* __restrict__ dst,
                          int* __restrict__ cursor, int* __restrict__ col, int e) {
    int i = blockIdx.x * blockDim.x + threadIdx.x;
    if (i < e) {
        int d = dst[i];
        int p = atomicAdd(&cursor[d], 1);
        col[p] = src[i];
    }
}

__device__ __forceinline__ uint32_t pack_bf16x2(float a, float b) {
    __nv_bfloat162 t = __floats2bfloat162_rn(a, b);
    return *reinterpret_cast<uint32_t*>(&t);
}

// z = h + sum neighbors, emitted directly as split-bf16 hi/lo.
// 8 nodes per 256-thread block; unroll-4 gather (MLP=4) — the ONE change vs R13.
__global__ void k_agg(const float* __restrict__ h, const int* __restrict__ rowptr,
                      const int* __restrict__ col,
                      __nv_bfloat16* __restrict__ zhi, __nv_bfloat16* __restrict__ zlo,
                      int n) {
    int node = blockIdx.x * 8 + (threadIdx.x >> 5);
    if (node >= n) return;
    int lane = threadIdx.x & 31;
    const float4* h4 = reinterpret_cast<const float4*>(h);
    float4 acc = h4[(size_t)node * 32 + lane];
    int s0 = rowptr[node], s1 = rowptr[node + 1];
    int j = s0;
    for (; j + 3 < s1; j += 4) {
        int c0 = __ldg(&col[j]),     c1 = __ldg(&col[j + 1]);
        int c2 = __ldg(&col[j + 2]), c3 = __ldg(&col[j + 3]);
        float4 v0 = __ldg(&h4[(size_t)c0 * 32 + lane]);
        float4 v1 = __ldg(&h4[(size_t)c1 * 32 + lane]);
        float4 v2 = __ldg(&h4[(size_t)c2 * 32 + lane]);
        float4 v3 = __ldg(&h4[(size_t)c3 * 32 + lane]);
        acc.x += (v0.x + v1.x) + (v2.x + v3.x);
        acc.y += (v0.y + v1.y) + (v2.y + v3.y);
        acc.z += (v0.z + v1.z) + (v2.z + v3.z);
        acc.w += (v0.w + v1.w) + (v2.w + v3.w);
    }
    for (; j < s1; j++) {
        int c = __ldg(&col[j]);
        float4 v = __ldg(&h4[(size_t)c * 32 + lane]);
        acc.x += v.x; acc.y += v.y; acc.z += v.z; acc.w += v.w;
    }
    uint2 hp, lp;
    hp.x = pack_bf16x2(acc.x, acc.y);
    hp.y = pack_bf16x2(acc.z, acc.w);
    float hx = __bfloat162float(__float2bfloat16(acc.x));
    float hy = __bfloat162float(__float2bfloat16(acc.y));
    float hz = __bfloat162float(__float2bfloat16(acc.z));
    float hw = __bfloat162float(__float2bfloat16(acc.w));
    lp.x = pack_bf16x2(acc.x - hx, acc.y - hy);
    lp.y = pack_bf16x2(acc.z - hz, acc.w - hw);
    reinterpret_cast<uint2*>(zhi)[(size_t)node * 32 + lane] = hp;
    reinterpret_cast<uint2*>(zlo)[(size_t)node * 32 + lane] = lp;
}

// ---------------- fused 2-GEMM layer: h = relu(relu(z@Wa+ba)@Wb+bb) -----------
// Block tile 128 rows x 128 cols; 8 warps (4m x 2n), warp tile 32x64; K=128.
// Z arrives pre-split (bf16 hi/lo) -> staging is pure cp.async. (R13 version.)
#define TSTR   272
#define SM_ZHI 0
#define SM_ZLO (128 * TSTR)                  // 34816
#define SM_WAHI (2 * 128 * TSTR)             // 69632
#define SM_WALO (SM_WAHI + 128 * TSTR)       // 104448
#define SM_WBHI (SM_WALO + 128 * TSTR)       // 139264
#define SM_WBLO (SM_WBHI + 128 * TSTR)       // 174080
#define SM_BA  (SM_WBLO + 128 * TSTR)        // 208896
#define SM_BB  (SM_BA + 512)                 // 209408
#define SMEM_L (SM_BB + 512)                 // 209920

__device__ __forceinline__ uint32_t smem_u32(const void* p) {
    uint32_t a;
    asm("{ .reg .u64 t; cvta.to.shared.u64 t, %1; cvt.u32.u64 %0, t; }" : "=r"(a) : "l"(p));
    return a;
}
__device__ __forceinline__ void ldsm_x4(uint32_t* r, uint32_t addr) {
    asm volatile("ldmatrix.sync.aligned.m8n8.x4.shared.b16 {%0,%1,%2,%3}, [%4];"
        : "=r"(r[0]), "=r"(r[1]), "=r"(r[2]), "=r"(r[3]) : "r"(addr));
}
__device__ __forceinline__ void mma_16816(float* c, const uint32_t* a, const uint32_t* b) {
    asm volatile(
        "mma.sync.aligned.m16n8k16.row.col.f32.bf16.bf16.f32 "
        "{%0,%1,%2,%3}, {%4,%5,%6,%7}, {%8,%9}, {%0,%1,%2,%3};"
        : "+f"(c[0]), "+f"(c[1]), "+f"(c[2]), "+f"(c[3])
        : "r"(a[0]), "r"(a[1]), "r"(a[2]), "r"(a[3]), "r"(b[0]), "r"(b[1]));
}
__device__ __forceinline__ void cp_async16(uint32_t saddr, const void* gptr) {
    asm volatile("cp.async.ca.shared.global [%0], [%1], 16;" :: "r"(saddr), "l"(gptr));
}

// One GEMM pass over the staged Z tiles against W tiles at (whi_ofs, wlo_ofs).
__device__ __forceinline__ void gemm_pass(uint32_t sb, uint32_t whi_ofs, uint32_t wlo_ofs,
                                          int lane, int m0, int n0, float acc[2][8][4]) {
#pragma unroll
    for (int a = 0; a < 2; a++)
#pragma unroll
        for (int b = 0; b < 8; b++)
#pragma unroll
            for (int c = 0; c < 4; c++) acc[a][b][c] = 0.f;

    const uint32_t a_row  = m0 + (lane & 15);
    const uint32_t a_coff = (lane >> 4) * 8;
    const uint32_t b_row  = n0 + ((lane >> 4) << 3) + (lane & 7);
    const uint32_t b_coff = ((lane >> 3) & 1) * 8;

#pragma unroll
    for (int ks = 0; ks < 8; ks++) {
        const int k = ks * 16;
        uint32_t ah[2][4], al[2][4];
#pragma unroll
        for (int mf = 0; mf < 2; mf++) {
            uint32_t addr = sb + SM_ZHI + (a_row + mf * 16) * TSTR + (k + a_coff) * 2;
            ldsm_x4(ah[mf], addr);
            ldsm_x4(al[mf], addr + (SM_ZLO - SM_ZHI));
        }
#pragma unroll
        for (int nfg = 0; nfg < 4; nfg++) {
            uint32_t baddr = sb + whi_ofs + (b_row + nfg * 16) * TSTR + (k + b_coff) * 2;
            uint32_t bh[4], bl[4];
            ldsm_x4(bh, baddr);
            ldsm_x4(bl, baddr + (wlo_ofs - whi_ofs));
#pragma unroll
            for (int mf = 0; mf < 2; mf++) {
                mma_16816(acc[mf][nfg * 2 + 0], ah[mf], bh + 0);
                mma_16816(acc[mf][nfg * 2 + 0], al[mf], bh + 0);
                mma_16816(acc[mf][nfg * 2 + 0], ah[mf], bl + 0);
                mma_16816(acc[mf][nfg * 2 + 1], ah[mf], bh + 2);
                mma_16816(acc[mf][nfg * 2 + 1], al[mf], bh + 2);
                mma_16816(acc[mf][nfg * 2 + 1], ah[mf], bl + 2);
            }
        }
    }
}

__global__ __launch_bounds__(256, 1)
void k_layer(const uint4* __restrict__ Zhi, const uint4* __restrict__ Zlo,
             const uint4* __restrict__ WaHi, const uint4* __restrict__ WaLo,
             const uint4* __restrict__ WbHi, const uint4* __restrict__ WbLo,
             const float* __restrict__ ba, const float* __restrict__ bb,
             float* __restrict__ C, int n) {
    extern __shared__ char sm[];
    const uint32_t sb = smem_u32(sm);
    const int tid = threadIdx.x;
    const int lane = tid & 31, w = tid >> 5;
    const int rowBase = blockIdx.x * 128;

    // ---- group 0: Z tiles + Wa (everything phase 1 needs), all cp.async ----
#pragma unroll
    for (int it = 0; it < 8; it++) {
        int j = tid + it * 256;              // 0..2047
        int row = j >> 4, chunk = j & 15;
        uint32_t dofs = row * TSTR + chunk * 16;
        size_t gofs = (size_t)(rowBase + row) * 16 + chunk;
        cp_async16(sb + SM_ZHI + dofs, Zhi + gofs);
        cp_async16(sb + SM_ZLO + dofs, Zlo + gofs);
    }
#pragma unroll
    for (int it = 0; it < 8; it++) {
        int j = tid + it * 256;
        int row = j >> 4, chunk = j & 15;
        uint32_t dofs = row * TSTR + chunk * 16;
        cp_async16(sb + SM_WAHI + dofs, WaHi + row * 16 + chunk);
        cp_async16(sb + SM_WALO + dofs, WaLo + row * 16 + chunk);
    }
    asm volatile("cp.async.commit_group;" ::: "memory");

    // ---- group 1: Wb (hidden under phase-1 compute) ----
#pragma unroll
    for (int it = 0; it < 8; it++) {
        int j = tid + it * 256;
        int row = j >> 4, chunk = j & 15;
        uint32_t dofs = row * TSTR + chunk * 16;
        cp_async16(sb + SM_WBHI + dofs, WbHi + row * 16 + chunk);
        cp_async16(sb + SM_WBLO + dofs, WbLo + row * 16 + chunk);
    }
    asm volatile("cp.async.commit_group;" ::: "memory");

    if (tid < 128) {
        reinterpret_cast<float*>(sm + SM_BA)[tid] = ba[tid];
        reinterpret_cast<float*>(sm + SM_BB)[tid] = bb[tid];
    }

    asm volatile("cp.async.wait_group 1;" ::: "memory");   // Z + Wa resident
    __syncthreads();

    const int m0 = (w >> 1) * 32, n0 = (w & 1) * 64;
    float acc[2][8][4];

    // ---- phase 1: acc1 = Z @ Wa ----
    gemm_pass(sb, SM_WAHI, SM_WALO, lane, m0, n0, acc);
    __syncthreads();                                       // all ldsm of Z done

    // ---- relu(acc1+ba) -> Z smem (bf16 hi/lo), each warp its own quadrant ----
    {
        const float* bav = reinterpret_cast<const float*>(sm + SM_BA);
#pragma unroll
        for (int mf = 0; mf < 2; mf++) {
#pragma unroll
            for (int nf = 0; nf < 8; nf++) {
                int r = m0 + mf * 16 + (lane >> 2);
                int c = n0 + nf * 8 + (lane & 3) * 2;
                float b0 = bav[c], b1 = bav[c + 1];
                float z0 = fmaxf(acc[mf][nf][0] + b0, 0.f);
                float z1 = fmaxf(acc[mf][nf][1] + b1, 0.f);
                float z2 = fmaxf(acc[mf][nf][2] + b0, 0.f);
                float z3 = fmaxf(acc[mf][nf][3] + b1, 0.f);
                float h0 = __bfloat162float(__float2bfloat16(z0));
                float h1 = __bfloat162float(__float2bfloat16(z1));
                float h2 = __bfloat162float(__float2bfloat16(z2));
                float h3 = __bfloat162float(__float2bfloat16(z3));
                *reinterpret_cast<uint32_t*>(sm + SM_ZHI + r * TSTR + c * 2) =
                    pack_bf16x2(z0, z1);
                *reinterpret_cast<uint32_t*>(sm + SM_ZLO + r * TSTR + c * 2) =
                    pack_bf16x2(z0 - h0, z1 - h1);
                *reinterpret_cast<uint32_t*>(sm + SM_ZHI + (r + 8) * TSTR + c * 2) =
                    pack_bf16x2(z2, z3);
                *reinterpret_cast<uint32_t*>(sm + SM_ZLO + (r + 8) * TSTR + c * 2) =
                    pack_bf16x2(z2 - h2, z3 - h3);
            }
        }
    }
    asm volatile("cp.async.wait_group 0;" ::: "memory");   // Wb resident
    __syncthreads();

    // ---- phase 2: acc2 = Z' @ Wb ----
    gemm_pass(sb, SM_WBHI, SM_WBLO, lane, m0, n0, acc);

    // ---- epilogue: relu(acc2+bb) -> global fp32 ----
    {
        const float* bbv = reinterpret_cast<const float*>(sm + SM_BB);
#pragma unroll
        for (int mf = 0; mf < 2; mf++) {
#pragma unroll
            for (int nf = 0; nf < 8; nf++) {
                int r = m0 + mf * 16 + (lane >> 2);
                int c = n0 + nf * 8 + (lane & 3) * 2;
                float b0 = bbv[c], b1 = bbv[c + 1];
                int gr0 = rowBase + r;
                if (gr0 < n) {
                    float2 v;
                    v.x = fmaxf(acc[mf][nf][0] + b0, 0.f);
                    v.y = fmaxf(acc[mf][nf][1] + b1, 0.f);
                    *reinterpret_cast<float2*>(C + (size_t)gr0 * 128 + c) = v;
                }
                int gr1 = gr0 + 8;
                if (gr1 < n) {
                    float2 v;
                    v.x = fmaxf(acc[mf][nf][2] + b0, 0.f);
                    v.y = fmaxf(acc[mf][nf][3] + b1, 0.f);
                    *reinterpret_cast<float2*>(C + (size_t)gr1 * 128 + c) = v;
                }
            }
        }
    }
}

// ---------------- pool + final -------------------------------------------------
__global__ void k_pool_partial(const float* __restrict__ h, float* __restrict__ part, int n) {
    int d = threadIdx.x;
    float acc = 0.f;
    for (int r = blockIdx.x; r < n; r += gridDim.x)
        acc += h[(size_t)r * D + d];
    part[blockIdx.x * D + d] = acc;
}

__global__ void k_final(const float* __restrict__ part, const float* __restrict__ Wlin,
                        const float* __restrict__ blin, float* __restrict__ out) {
    __shared__ float pooled[D];
    int t = threadIdx.x;
    float acc = 0.f;
    for (int p = 0; p < NPART; p++) acc += part[p * D + t];
    pooled[t] = acc;
    __syncthreads();
    float o = blin[t];
    for (int d = 0; d < D; d++) o = fmaf(pooled[d], Wlin[d * D + t], o);
    out[t] = o;
}

// ---------------- launch -------------------------------------------------------
extern "C" void kernel_launch(void* const* d_in, const int* in_sizes, int n_in,
                              void* d_out, int out_size) {
    const int*   x    = (const int*)d_in[0];
    const int*   ei   = (const int*)d_in[1];
    const float* emb  = (const float*)d_in[2];
    const float* Wa   = (const float*)d_in[3];
    const float* ba   = (const float*)d_in[4];
    const float* Wb   = (const float*)d_in[5];
    const float* bb   = (const float*)d_in[6];
    const float* Wlin = (const float*)d_in[7];
    const float* blin = (const float*)d_in[8];
    float* out = (float*)d_out;

    const int N = in_sizes[0];
    const int E = in_sizes[1] / 2;
    const int* src = ei;
    const int* dst = ei + E;

    float *A, *part;
    __nv_bfloat16 *zhi, *zlo;
    int *deg, *rowptr, *cursor, *col, *bsum, *boff;
    uint4 *whi, *wlo;
    cudaGetSymbolAddress((void**)&A, g_bufA);
    cudaGetSymbolAddress((void**)&zhi, g_zhi);
    cudaGetSymbolAddress((void**)&zlo, g_zlo);
    cudaGetSymbolAddress((void**)&deg, g_deg);
    cudaGetSymbolAddress((void**)&rowptr, g_rowptr);
    cudaGetSymbolAddress((void**)&cursor, g_cursor);
    cudaGetSymbolAddress((void**)&col, g_col);
    cudaGetSymbolAddress((void**)&part, g_part);
    cudaGetSymbolAddress((void**)&bsum, g_bsum);
    cudaGetSymbolAddress((void**)&boff, g_boff);
    cudaGetSymbolAddress((void**)&whi, g_WhiT);
    cudaGetSymbolAddress((void**)&wlo, g_WloT);

    cudaFuncSetAttribute(k_layer, cudaFuncAttributeMaxDynamicSharedMemorySize, SMEM_L);

    // h = emb[x]
    k_gather<<<(N * 32 + 255) / 256, 256>>>(x, emb, A, N);

    // pre-split weights to transposed bf16 hi/lo
    k_wsplit<<<40, 128>>>(Wa, Wb, (__nv_bfloat16*)whi, (__nv_bfloat16*)wlo);

    // CSR build
    k_zero_int<<<(N + 255) / 256, 256>>>(deg, N);
    k_count<<<(E + 255) / 256, 256>>>(dst, deg, E);
    const int nb = (N + SCAN_BLK - 1) / SCAN_BLK;
    k_scan_blk<<<nb, SCAN_BLK>>>(deg, rowptr, bsum, N);
    k_scan_top<<<1, 128>>>(bsum, boff, rowptr + N, nb);
    k_scan_add<<<(N + 255) / 256, 256>>>(rowptr, cursor, boff, N);
    k_scatter<<<(E + 255) / 256, 256>>>(src, dst, cursor, col, E);

    const int layer_blocks = (N + 127) / 128;
    const int agg_blocks   = (N + 7) / 8;
    for (int l = 0; l < L_LAYERS; l++) {
        // z = h + agg(h), emitted as split-bf16
        k_agg<<<agg_blocks, 256>>>(A, rowptr, col, zhi, zlo, N);
        // h = relu(relu(z@Wa+ba)@Wb+bb)
        k_layer<<<layer_blocks, 256, SMEM_L>>>(
            (const uint4*)zhi, (const uint4*)zlo,
            whi + (size_t)l * 2048, wlo + (size_t)l * 2048,
            whi + (size_t)(5 + l) * 2048, wlo + (size_t)(5 + l) * 2048,
            ba + l * D, bb + l * D, A, N);
    }

    k_pool_partial<<<NPART, 128>>>(A, part, N);
    k_final<<<1, 128>>>(part, Wlin, blin, out);
}

// round 16
// speedup vs baseline: 1.3118x; 1.1873x over previous
#include <cuda_runtime.h>
#include <cuda_bf16.h>
#include <cuda_fp16.h>
#include <cstdint>

// Problem constants
#define MAXN 100000
#define MAXE 600000
#define D 128
#define L_LAYERS 5
#define NPART 296
#define SCAN_BLK 1024

// ---------------- scratch (device globals; no allocation allowed) -------------
// h stored as fp16 (2B/elem) — halves all agg/pool/gather traffic.
__device__ __align__(16) __half g_h16[(MAXN + 128) * D];
// aggregated z in split-bf16 (padded by 128 rows so tail-tile cp.async stays in-bounds)
__device__ __align__(16) __nv_bfloat16 g_zhi[(MAXN + 128) * D];
__device__ __align__(16) __nv_bfloat16 g_zlo[(MAXN + 128) * D];
__device__ int   g_deg[MAXN];
__device__ int   g_rowptr[MAXN + 1];
__device__ int   g_cursor[MAXN];
__device__ int   g_col[MAXE];
__device__ float g_part[NPART * D];
__device__ int   g_bsum[128];
__device__ int   g_boff[128];
// pre-split transposed weights: 10 matrices x 128x128 bf16 (as uint4)
__device__ uint4 g_WhiT[10 * 128 * 128 / 8];
__device__ uint4 g_WloT[10 * 128 * 128 / 8];

// ---------------- utility kernels --------------------------------------------
__global__ void k_zero_int(int* __restrict__ p, int n) {
    int i = blockIdx.x * blockDim.x + threadIdx.x;
    if (i < n) p[i] = 0;
}

// h16[n,:] = fp16(emb[x[n],:]) — thread handles 8 cols
__global__ void k_gather(const int* __restrict__ x, const float* __restrict__ emb,
                         __half* __restrict__ h, int n) {
    int i = blockIdx.x * blockDim.x + threadIdx.x;   // over n*16
    if (i < n * 16) {
        int node = i >> 4, q = i & 15;
        const float4* e = reinterpret_cast<const float4*>(emb) + (size_t)__ldg(&x[node]) * 32 + q * 2;
        float4 a = __ldg(e), b = __ldg(e + 1);
        __half2 p0 = __floats2half2_rn(a.x, a.y);
        __half2 p1 = __floats2half2_rn(a.z, a.w);
        __half2 p2 = __floats2half2_rn(b.x, b.y);
        __half2 p3 = __floats2half2_rn(b.z, b.w);
        uint4 o;
        o.x = *reinterpret_cast<uint32_t*>(&p0);
        o.y = *reinterpret_cast<uint32_t*>(&p1);
        o.z = *reinterpret_cast<uint32_t*>(&p2);
        o.w = *reinterpret_cast<uint32_t*>(&p3);
        reinterpret_cast<uint4*>(h)[(size_t)node * 16 + q] = o;
    }
}

__global__ void k_count(const int* __restrict__ dst, int* __restrict__ deg, int e) {
    int i = blockIdx.x * blockDim.x + threadIdx.x;
    if (i < e) atomicAdd(&deg[dst[i]], 1);
}

// split + transpose weights: WT[n][k] = split(W[k][n]); 40 blocks (mat, k-quarter)
__global__ void k_wsplit(const float* __restrict__ Wa, const float* __restrict__ Wb,
                         __nv_bfloat16* __restrict__ hi, __nv_bfloat16* __restrict__ lo) {
    int mat = blockIdx.x >> 2, kq = blockIdx.x & 3;
    const float* W = (mat < 5) ? (Wa + mat * 16384) : (Wb + (mat - 5) * 16384);
    __nv_bfloat16* H  = hi + mat * 16384;
    __nv_bfloat16* Lo = lo + mat * 16384;
    int nidx = threadIdx.x;
    for (int k = kq * 32; k < kq * 32 + 32; k++) {
        float x = W[k * 128 + nidx];
        __nv_bfloat16 h = __float2bfloat16(x);
        H[nidx * 128 + k]  = h;
        Lo[nidx * 128 + k] = __float2bfloat16(x - __bfloat162float(h));
    }
}

// ---- 3-phase scan -------------------------------------------------------------
__global__ void k_scan_blk(const int* __restrict__ deg, int* __restrict__ rowptr,
                           int* __restrict__ bsum, int n) {
    int i = blockIdx.x * SCAN_BLK + threadIdx.x;
    int lane = threadIdx.x & 31, wid = threadIdx.x >> 5;
    int v = (i < n) ? deg[i] : 0;
    int inc = v;
#pragma unroll
    for (int o = 1; o < 32; o <<= 1) {
        int t = __shfl_up_sync(0xFFFFFFFFu, inc, o);
        if (lane >= o) inc += t;
    }
    __shared__ int wsum[32];
    if (lane == 31) wsum[wid] = inc;
    __syncthreads();
    if (wid == 0) {
        int s = wsum[lane];
#pragma unroll
        for (int o = 1; o < 32; o <<= 1) {
            int t = __shfl_up_sync(0xFFFFFFFFu, s, o);
            if (lane >= o) s += t;
        }
        wsum[lane] = s;
    }
    __syncthreads();
    int base = (wid > 0) ? wsum[wid - 1] : 0;
    if (i < n) rowptr[i] = base + inc - v;
    if (threadIdx.x == SCAN_BLK - 1) bsum[blockIdx.x] = base + inc;
}

__global__ void k_scan_top(const int* __restrict__ bsum, int* __restrict__ boff,
                           int* __restrict__ total_out, int nb) {
    int t = threadIdx.x, lane = t & 31, wid = t >> 5;
    int v = (t < nb) ? bsum[t] : 0;
    int inc = v;
#pragma unroll
    for (int o = 1; o < 32; o <<= 1) {
        int u = __shfl_up_sync(0xFFFFFFFFu, inc, o);
        if (lane >= o) inc += u;
    }
    __shared__ int ws[32];
    __shared__ int wsx[33];
    if (lane == 31) ws[wid] = inc;
    __syncthreads();
    if (t == 0) {
        wsx[0] = 0;
        for (int w = 0; w < 4; w++) wsx[w + 1] = wsx[w] + ws[w];
    }
    __syncthreads();
    int excl = wsx[wid] + inc - v;
    if (t < nb) boff[t] = excl;
    if (t == blockDim.x - 1) *total_out = wsx[4];
}

__global__ void k_scan_add(int* __restrict__ rowptr, int* __restrict__ cursor,
                           const int* __restrict__ boff, int n) {
    int i = blockIdx.x * blockDim.x + threadIdx.x;
    if (i < n) {
        int r = rowptr[i] + boff[i >> 10];
        rowptr[i] = r;
        cursor[i] = r;
    }
}

__global__ void k_scatter(const int* __restrict__ src, const int* __restrict__ dst,
                          int* __restrict__ cursor, int* __restrict__ col, int e) {
    int i = blockIdx.x * blockDim.x + threadIdx.x;
    if (i < e) {
        int d = dst[i];
        int p = atomicAdd(&cursor[d], 1);
        col[p] = src[i];
    }
}

__device__ __forceinline__ uint32_t pack_bf16x2(float a, float b) {
    __nv_bfloat162 t = __floats2bfloat162_rn(a, b);
    return *reinterpret_cast<uint32_t*>(&t);
}

__device__ __forceinline__ float4 h4_to_f4(uint2 u) {
    __half2 a = *reinterpret_cast<__half2*>(&u.x);
    __half2 b = *reinterpret_cast<__half2*>(&u.y);
    float2 fa = __half22float2(a), fb = __half22float2(b);
    return make_float4(fa.x, fa.y, fb.x, fb.y);
}

// z = h + sum neighbors (h in fp16, fp32 accumulate), emitted as split-bf16.
// 8 nodes per 256-thread block; unroll-2 gather (R13 schedule — proven best).
__global__ void k_agg(const __half* __restrict__ h, const int* __restrict__ rowptr,
                      const int* __restrict__ col,
                      __nv_bfloat16* __restrict__ zhi, __nv_bfloat16* __restrict__ zlo,
                      int n) {
    int node = blockIdx.x * 8 + (threadIdx.x >> 5);
    if (node >= n) return;
    int lane = threadIdx.x & 31;                 // lane covers cols 4*lane..4*lane+3
    const uint2* h2 = reinterpret_cast<const uint2*>(h);
    float4 acc = h4_to_f4(__ldg(&h2[(size_t)node * 32 + lane]));
    int s0 = rowptr[node], s1 = rowptr[node + 1];
    int j = s0;
    for (; j + 1 < s1; j += 2) {
        int c0 = __ldg(&col[j]), c1 = __ldg(&col[j + 1]);
        float4 v0 = h4_to_f4(__ldg(&h2[(size_t)c0 * 32 + lane]));
        float4 v1 = h4_to_f4(__ldg(&h2[(size_t)c1 * 32 + lane]));
        acc.x += v0.x + v1.x; acc.y += v0.y + v1.y;
        acc.z += v0.z + v1.z; acc.w += v0.w + v1.w;
    }
    if (j < s1) {
        int c = __ldg(&col[j]);
        float4 v = h4_to_f4(__ldg(&h2[(size_t)c * 32 + lane]));
        acc.x += v.x; acc.y += v.y; acc.z += v.z; acc.w += v.w;
    }
    uint2 hp, lp;
    hp.x = pack_bf16x2(acc.x, acc.y);
    hp.y = pack_bf16x2(acc.z, acc.w);
    float hx = __bfloat162float(__float2bfloat16(acc.x));
    float hy = __bfloat162float(__float2bfloat16(acc.y));
    float hz = __bfloat162float(__float2bfloat16(acc.z));
    float hw = __bfloat162float(__float2bfloat16(acc.w));
    lp.x = pack_bf16x2(acc.x - hx, acc.y - hy);
    lp.y = pack_bf16x2(acc.z - hz, acc.w - hw);
    reinterpret_cast<uint2*>(zhi)[(size_t)node * 32 + lane] = hp;
    reinterpret_cast<uint2*>(zlo)[(size_t)node * 32 + lane] = lp;
}

// ---------------- fused 2-GEMM layer: h = relu(relu(z@Wa+ba)@Wb+bb) -----------
// Block tile 128 rows x 128 cols; 8 warps (4m x 2n), warp tile 32x64; K=128.
// Z arrives pre-split (bf16 hi/lo) -> staging is pure cp.async. (R13 version.)
#define TSTR   272
#define SM_ZHI 0
#define SM_ZLO (128 * TSTR)                  // 34816
#define SM_WAHI (2 * 128 * TSTR)             // 69632
#define SM_WALO (SM_WAHI + 128 * TSTR)       // 104448
#define SM_WBHI (SM_WALO + 128 * TSTR)       // 139264
#define SM_WBLO (SM_WBHI + 128 * TSTR)       // 174080
#define SM_BA  (SM_WBLO + 128 * TSTR)        // 208896
#define SM_BB  (SM_BA + 512)                 // 209408
#define SMEM_L (SM_BB + 512)                 // 209920

__device__ __forceinline__ uint32_t smem_u32(const void* p) {
    uint32_t a;
    asm("{ .reg .u64 t; cvta.to.shared.u64 t, %1; cvt.u32.u64 %0, t; }" : "=r"(a) : "l"(p));
    return a;
}
__device__ __forceinline__ void ldsm_x4(uint32_t* r, uint32_t addr) {
    asm volatile("ldmatrix.sync.aligned.m8n8.x4.shared.b16 {%0,%1,%2,%3}, [%4];"
        : "=r"(r[0]), "=r"(r[1]), "=r"(r[2]), "=r"(r[3]) : "r"(addr));
}
__device__ __forceinline__ void mma_16816(float* c, const uint32_t* a, const uint32_t* b) {
    asm volatile(
        "mma.sync.aligned.m16n8k16.row.col.f32.bf16.bf16.f32 "
        "{%0,%1,%2,%3}, {%4,%5,%6,%7}, {%8,%9}, {%0,%1,%2,%3};"
        : "+f"(c[0]), "+f"(c[1]), "+f"(c[2]), "+f"(c[3])
        : "r"(a[0]), "r"(a[1]), "r"(a[2]), "r"(a[3]), "r"(b[0]), "r"(b[1]));
}
__device__ __forceinline__ void cp_async16(uint32_t saddr, const void* gptr) {
    asm volatile("cp.async.ca.shared.global [%0], [%1], 16;" :: "r"(saddr), "l"(gptr));
}

// One GEMM pass over the staged Z tiles against W tiles at (whi_ofs, wlo_ofs).
__device__ __forceinline__ void gemm_pass(uint32_t sb, uint32_t whi_ofs, uint32_t wlo_ofs,
                                          int lane, int m0, int n0, float acc[2][8][4]) {
#pragma unroll
    for (int a = 0; a < 2; a++)
#pragma unroll
        for (int b = 0; b < 8; b++)
#pragma unroll
            for (int c = 0; c < 4; c++) acc[a][b][c] = 0.f;

    const uint32_t a_row  = m0 + (lane & 15);
    const uint32_t a_coff = (lane >> 4) * 8;
    const uint32_t b_row  = n0 + ((lane >> 4) << 3) + (lane & 7);
    const uint32_t b_coff = ((lane >> 3) & 1) * 8;

#pragma unroll
    for (int ks = 0; ks < 8; ks++) {
        const int k = ks * 16;
        uint32_t ah[2][4], al[2][4];
#pragma unroll
        for (int mf = 0; mf < 2; mf++) {
            uint32_t addr = sb + SM_ZHI + (a_row + mf * 16) * TSTR + (k + a_coff) * 2;
            ldsm_x4(ah[mf], addr);
            ldsm_x4(al[mf], addr + (SM_ZLO - SM_ZHI));
        }
#pragma unroll
        for (int nfg = 0; nfg < 4; nfg++) {
            uint32_t baddr = sb + whi_ofs + (b_row + nfg * 16) * TSTR + (k + b_coff) * 2;
            uint32_t bh[4], bl[4];
            ldsm_x4(bh, baddr);
            ldsm_x4(bl, baddr + (wlo_ofs - whi_ofs));
#pragma unroll
            for (int mf = 0; mf < 2; mf++) {
                mma_16816(acc[mf][nfg * 2 + 0], ah[mf], bh + 0);
                mma_16816(acc[mf][nfg * 2 + 0], al[mf], bh + 0);
                mma_16816(acc[mf][nfg * 2 + 0], ah[mf], bl + 0);
                mma_16816(acc[mf][nfg * 2 + 1], ah[mf], bh + 2);
                mma_16816(acc[mf][nfg * 2 + 1], al[mf], bh + 2);
                mma_16816(acc[mf][nfg * 2 + 1], ah[mf], bl + 2);
            }
        }
    }
}

__global__ __launch_bounds__(256, 1)
void k_layer(const uint4* __restrict__ Zhi, const uint4* __restrict__ Zlo,
             const uint4* __restrict__ WaHi, const uint4* __restrict__ WaLo,
             const uint4* __restrict__ WbHi, const uint4* __restrict__ WbLo,
             const float* __restrict__ ba, const float* __restrict__ bb,
             __half* __restrict__ C16, int n) {
    extern __shared__ char sm[];
    const uint32_t sb = smem_u32(sm);
    const int tid = threadIdx.x;
    const int lane = tid & 31, w = tid >> 5;
    const int rowBase = blockIdx.x * 128;

    // ---- group 0: Z tiles + Wa (everything phase 1 needs), all cp.async ----
#pragma unroll
    for (int it = 0; it < 8; it++) {
        int j = tid + it * 256;              // 0..2047
        int row = j >> 4, chunk = j & 15;
        uint32_t dofs = row * TSTR + chunk * 16;
        size_t gofs = (size_t)(rowBase + row) * 16 + chunk;
        cp_async16(sb + SM_ZHI + dofs, Zhi + gofs);
        cp_async16(sb + SM_ZLO + dofs, Zlo + gofs);
    }
#pragma unroll
    for (int it = 0; it < 8; it++) {
        int j = tid + it * 256;
        int row = j >> 4, chunk = j & 15;
        uint32_t dofs = row * TSTR + chunk * 16;
        cp_async16(sb + SM_WAHI + dofs, WaHi + row * 16 + chunk);
        cp_async16(sb + SM_WALO + dofs, WaLo + row * 16 + chunk);
    }
    asm volatile("cp.async.commit_group;" ::: "memory");

    // ---- group 1: Wb (hidden under phase-1 compute) ----
#pragma unroll
    for (int it = 0; it < 8; it++) {
        int j = tid + it * 256;
        int row = j >> 4, chunk = j & 15;
        uint32_t dofs = row * TSTR + chunk * 16;
        cp_async16(sb + SM_WBHI + dofs, WbHi + row * 16 + chunk);
        cp_async16(sb + SM_WBLO + dofs, WbLo + row * 16 + chunk);
    }
    asm volatile("cp.async.commit_group;" ::: "memory");

    if (tid < 128) {
        reinterpret_cast<float*>(sm + SM_BA)[tid] = ba[tid];
        reinterpret_cast<float*>(sm + SM_BB)[tid] = bb[tid];
    }

    asm volatile("cp.async.wait_group 1;" ::: "memory");   // Z + Wa resident
    __syncthreads();

    const int m0 = (w >> 1) * 32, n0 = (w & 1) * 64;
    float acc[2][8][4];

    // ---- phase 1: acc1 = Z @ Wa ----
    gemm_pass(sb, SM_WAHI, SM_WALO, lane, m0, n0, acc);
    __syncthreads();                                       // all ldsm of Z done

    // ---- relu(acc1+ba) -> Z smem (bf16 hi/lo), each warp its own quadrant ----
    {
        const float* bav = reinterpret_cast<const float*>(sm + SM_BA);
#pragma unroll
        for (int mf = 0; mf < 2; mf++) {
#pragma unroll
            for (int nf = 0; nf < 8; nf++) {
                int r = m0 + mf * 16 + (lane >> 2);
                int c = n0 + nf * 8 + (lane & 3) * 2;
                float b0 = bav[c], b1 = bav[c + 1];
                float z0 = fmaxf(acc[mf][nf][0] + b0, 0.f);
                float z1 = fmaxf(acc[mf][nf][1] + b1, 0.f);
                float z2 = fmaxf(acc[mf][nf][2] + b0, 0.f);
                float z3 = fmaxf(acc[mf][nf][3] + b1, 0.f);
                float h0 = __bfloat162float(__float2bfloat16(z0));
                float h1 = __bfloat162float(__float2bfloat16(z1));
                float h2 = __bfloat162float(__float2bfloat16(z2));
                float h3 = __bfloat162float(__float2bfloat16(z3));
                *reinterpret_cast<uint32_t*>(sm + SM_ZHI + r * TSTR + c * 2) =
                    pack_bf16x2(z0, z1);
                *reinterpret_cast<uint32_t*>(sm + SM_ZLO + r * TSTR + c * 2) =
                    pack_bf16x2(z0 - h0, z1 - h1);
                *reinterpret_cast<uint32_t*>(sm + SM_ZHI + (r + 8) * TSTR + c * 2) =
                    pack_bf16x2(z2, z3);
                *reinterpret_cast<uint32_t*>(sm + SM_ZLO + (r + 8) * TSTR + c * 2) =
                    pack_bf16x2(z2 - h2, z3 - h3);
            }
        }
    }
    asm volatile("cp.async.wait_group 0;" ::: "memory");   // Wb resident
    __syncthreads();

    // ---- phase 2: acc2 = Z' @ Wb ----
    gemm_pass(sb, SM_WBHI, SM_WBLO, lane, m0, n0, acc);

    // ---- epilogue: relu(acc2+bb) -> global fp16 ----
    {
        const float* bbv = reinterpret_cast<const float*>(sm + SM_BB);
#pragma unroll
        for (int mf = 0; mf < 2; mf++) {
#pragma unroll
            for (int nf = 0; nf < 8; nf++) {
                int r = m0 + mf * 16 + (lane >> 2);
                int c = n0 + nf * 8 + (lane & 3) * 2;
                float b0 = bbv[c], b1 = bbv[c + 1];
                int gr0 = rowBase + r;
                if (gr0 < n) {
                    __half2 v = __floats2half2_rn(fmaxf(acc[mf][nf][0] + b0, 0.f),
                                                  fmaxf(acc[mf][nf][1] + b1, 0.f));
                    *reinterpret_cast<__half2*>(C16 + (size_t)gr0 * 128 + c) = v;
                }
                int gr1 = gr0 + 8;
                if (gr1 < n) {
                    __half2 v = __floats2half2_rn(fmaxf(acc[mf][nf][2] + b0, 0.f),
                                                  fmaxf(acc[mf][nf][3] + b1, 0.f));
                    *reinterpret_cast<__half2*>(C16 + (size_t)gr1 * 128 + c) = v;
                }
            }
        }
    }
}

// ---------------- pool + final -------------------------------------------------
__global__ void k_pool_partial(const __half* __restrict__ h, float* __restrict__ part, int n) {
    int d = threadIdx.x;
    float acc = 0.f;
    for (int r = blockIdx.x; r < n; r += gridDim.x)
        acc += __half2float(__ldg(&h[(size_t)r * D + d]));
    part[blockIdx.x * D + d] = acc;
}

__global__ void k_final(const float* __restrict__ part, const float* __restrict__ Wlin,
                        const float* __restrict__ blin, float* __restrict__ out) {
    __shared__ float pooled[D];
    int t = threadIdx.x;
    float acc = 0.f;
    for (int p = 0; p < NPART; p++) acc += part[p * D + t];
    pooled[t] = acc;
    __syncthreads();
    float o = blin[t];
    for (int d = 0; d < D; d++) o = fmaf(pooled[d], Wlin[d * D + t], o);
    out[t] = o;
}

// ---------------- launch -------------------------------------------------------
extern "C" void kernel_launch(void* const* d_in, const int* in_sizes, int n_in,
                              void* d_out, int out_size) {
    const int*   x    = (const int*)d_in[0];
    const int*   ei   = (const int*)d_in[1];
    const float* emb  = (const float*)d_in[2];
    const float* Wa   = (const float*)d_in[3];
    const float* ba   = (const float*)d_in[4];
    const float* Wb   = (const float*)d_in[5];
    const float* bb   = (const float*)d_in[6];
    const float* Wlin = (const float*)d_in[7];
    const float* blin = (const float*)d_in[8];
    float* out = (float*)d_out;

    const int N = in_sizes[0];
    const int E = in_sizes[1] / 2;
    const int* src = ei;
    const int* dst = ei + E;

    float *part;
    __half *h16;
    __nv_bfloat16 *zhi, *zlo;
    int *deg, *rowptr, *cursor, *col, *bsum, *boff;
    uint4 *whi, *wlo;
    cudaGetSymbolAddress((void**)&h16, g_h16);
    cudaGetSymbolAddress((void**)&zhi, g_zhi);
    cudaGetSymbolAddress((void**)&zlo, g_zlo);
    cudaGetSymbolAddress((void**)&deg, g_deg);
    cudaGetSymbolAddress((void**)&rowptr, g_rowptr);
    cudaGetSymbolAddress((void**)&cursor, g_cursor);
    cudaGetSymbolAddress((void**)&col, g_col);
    cudaGetSymbolAddress((void**)&part, g_part);
    cudaGetSymbolAddress((void**)&bsum, g_bsum);
    cudaGetSymbolAddress((void**)&boff, g_boff);
    cudaGetSymbolAddress((void**)&whi, g_WhiT);
    cudaGetSymbolAddress((void**)&wlo, g_WloT);

    cudaFuncSetAttribute(k_layer, cudaFuncAttributeMaxDynamicSharedMemorySize, SMEM_L);

    // h = fp16(emb[x])
    k_gather<<<(N * 16 + 255) / 256, 256>>>(x, emb, h16, N);

    // pre-split weights to transposed bf16 hi/lo
    k_wsplit<<<40, 128>>>(Wa, Wb, (__nv_bfloat16*)whi, (__nv_bfloat16*)wlo);

    // CSR build
    k_zero_int<<<(N + 255) / 256, 256>>>(deg, N);
    k_count<<<(E + 255) / 256, 256>>>(dst, deg, E);
    const int nb = (N + SCAN_BLK - 1) / SCAN_BLK;
    k_scan_blk<<<nb, SCAN_BLK>>>(deg, rowptr, bsum, N);
    k_scan_top<<<1, 128>>>(bsum, boff, rowptr + N, nb);
    k_scan_add<<<(N + 255) / 256, 256>>>(rowptr, cursor, boff, N);
    k_scatter<<<(E + 255) / 256, 256>>>(src, dst, cursor, col, E);

    const int layer_blocks = (N + 127) / 128;
    const int agg_blocks   = (N + 7) / 8;
    for (int l = 0; l < L_LAYERS; l++) {
        // z = h + agg(h), fp32 accumulate, emitted as split-bf16
        k_agg<<<agg_blocks, 256>>>(h16, rowptr, col, zhi, zlo, N);
        // h = fp16(relu(relu(z@Wa+ba)@Wb+bb))
        k_layer<<<layer_blocks, 256, SMEM_L>>>(
            (const uint4*)zhi, (const uint4*)zlo,
            whi + (size_t)l * 2048, wlo + (size_t)l * 2048,
            whi + (size_t)(5 + l) * 2048, wlo + (size_t)(5 + l) * 2048,
            ba + l * D, bb + l * D, h16, N);
    }

    k_pool_partial<<<NPART, 128>>>(h16, part, N);
    k_final<<<1, 128>>>(part, Wlin, blin, out);
}

// round 17
// speedup vs baseline: 1.6343x; 1.2459x over previous
#include <cuda_runtime.h>
#include <cuda_bf16.h>
#include <cuda_fp16.h>
#include <cstdint>

// Problem constants
#define MAXN 100000
#define MAXE 600000
#define D 128
#define L_LAYERS 5
#define NPART 296
#define SCAN_BLK 1024

// ---------------- scratch (device globals; no allocation allowed) -------------
// h stored as fp16 (2B/elem); z stored as single fp16 too (noise pools away).
__device__ __align__(16) __half g_h16[(MAXN + 128) * D];
__device__ __align__(16) __half g_z16[(MAXN + 128) * D];
__device__ int   g_deg[MAXN];
__device__ int   g_rowptr[MAXN + 1];
__device__ int   g_cursor[MAXN];
__device__ int   g_col[MAXE];
__device__ float g_part[NPART * D];
__device__ int   g_bsum[128];
__device__ int   g_boff[128];
// pre-split transposed weights: 10 matrices x 128x128 fp16 hi/lo (as uint4)
__device__ uint4 g_WhiT[10 * 128 * 128 / 8];
__device__ uint4 g_WloT[10 * 128 * 128 / 8];

// ---------------- utility kernels --------------------------------------------
__global__ void k_zero_int(int* __restrict__ p, int n) {
    int i = blockIdx.x * blockDim.x + threadIdx.x;
    if (i < n) p[i] = 0;
}

// h16[n,:] = fp16(emb[x[n],:]) — thread handles 8 cols
__global__ void k_gather(const int* __restrict__ x, const float* __restrict__ emb,
                         __half* __restrict__ h, int n) {
    int i = blockIdx.x * blockDim.x + threadIdx.x;   // over n*16
    if (i < n * 16) {
        int node = i >> 4, q = i & 15;
        const float4* e = reinterpret_cast<const float4*>(emb) + (size_t)__ldg(&x[node]) * 32 + q * 2;
        float4 a = __ldg(e), b = __ldg(e + 1);
        __half2 p0 = __floats2half2_rn(a.x, a.y);
        __half2 p1 = __floats2half2_rn(a.z, a.w);
        __half2 p2 = __floats2half2_rn(b.x, b.y);
        __half2 p3 = __floats2half2_rn(b.z, b.w);
        uint4 o;
        o.x = *reinterpret_cast<uint32_t*>(&p0);
        o.y = *reinterpret_cast<uint32_t*>(&p1);
        o.z = *reinterpret_cast<uint32_t*>(&p2);
        o.w = *reinterpret_cast<uint32_t*>(&p3);
        reinterpret_cast<uint4*>(h)[(size_t)node * 16 + q] = o;
    }
}

__global__ void k_count(const int* __restrict__ dst, int* __restrict__ deg, int e) {
    int i = blockIdx.x * blockDim.x + threadIdx.x;
    if (i < e) atomicAdd(&deg[dst[i]], 1);
}

// split + transpose weights to fp16 hi/lo: WT[n][k] = split(W[k][n])
__global__ void k_wsplit(const float* __restrict__ Wa, const float* __restrict__ Wb,
                         __half* __restrict__ hi, __half* __restrict__ lo) {
    int mat = blockIdx.x >> 2, kq = blockIdx.x & 3;
    const float* W = (mat < 5) ? (Wa + mat * 16384) : (Wb + (mat - 5) * 16384);
    __half* H  = hi + mat * 16384;
    __half* Lo = lo + mat * 16384;
    int nidx = threadIdx.x;
    for (int k = kq * 32; k < kq * 32 + 32; k++) {
        float x = W[k * 128 + nidx];
        __half h = __float2half_rn(x);
        H[nidx * 128 + k]  = h;
        Lo[nidx * 128 + k] = __float2half_rn(x - __half2float(h));
    }
}

// ---- 3-phase scan -------------------------------------------------------------
__global__ void k_scan_blk(const int* __restrict__ deg, int* __restrict__ rowptr,
                           int* __restrict__ bsum, int n) {
    int i = blockIdx.x * SCAN_BLK + threadIdx.x;
    int lane = threadIdx.x & 31, wid = threadIdx.x >> 5;
    int v = (i < n) ? deg[i] : 0;
    int inc = v;
#pragma unroll
    for (int o = 1; o < 32; o <<= 1) {
        int t = __shfl_up_sync(0xFFFFFFFFu, inc, o);
        if (lane >= o) inc += t;
    }
    __shared__ int wsum[32];
    if (lane == 31) wsum[wid] = inc;
    __syncthreads();
    if (wid == 0) {
        int s = wsum[lane];
#pragma unroll
        for (int o = 1; o < 32; o <<= 1) {
            int t = __shfl_up_sync(0xFFFFFFFFu, s, o);
            if (lane >= o) s += t;
        }
        wsum[lane] = s;
    }
    __syncthreads();
    int base = (wid > 0) ? wsum[wid - 1] : 0;
    if (i < n) rowptr[i] = base + inc - v;
    if (threadIdx.x == SCAN_BLK - 1) bsum[blockIdx.x] = base + inc;
}

__global__ void k_scan_top(const int* __restrict__ bsum, int* __restrict__ boff,
                           int* __restrict__ total_out, int nb) {
    int t = threadIdx.x, lane = t & 31, wid = t >> 5;
    int v = (t < nb) ? bsum[t] : 0;
    int inc = v;
#pragma unroll
    for (int o = 1; o < 32; o <<= 1) {
        int u = __shfl_up_sync(0xFFFFFFFFu, inc, o);
        if (lane >= o) inc += u;
    }
    __shared__ int ws[32];
    __shared__ int wsx[33];
    if (lane == 31) ws[wid] = inc;
    __syncthreads();
    if (t == 0) {
        wsx[0] = 0;
        for (int w = 0; w < 4; w++) wsx[w + 1] = wsx[w] + ws[w];
    }
    __syncthreads();
    int excl = wsx[wid] + inc - v;
    if (t < nb) boff[t] = excl;
    if (t == blockDim.x - 1) *total_out = wsx[4];
}

__global__ void k_scan_add(int* __restrict__ rowptr, int* __restrict__ cursor,
                           const int* __restrict__ boff, int n) {
    int i = blockIdx.x * blockDim.x + threadIdx.x;
    if (i < n) {
        int r = rowptr[i] + boff[i >> 10];
        rowptr[i] = r;
        cursor[i] = r;
    }
}

__global__ void k_scatter(const int* __restrict__ src, const int* __restrict__ dst,
                          int* __restrict__ cursor, int* __restrict__ col, int e) {
    int i = blockIdx.x * blockDim.x + threadIdx.x;
    if (i < e) {
        int d = dst[i];
        int p = atomicAdd(&cursor[d], 1);
        col[p] = src[i];
    }
}

__device__ __forceinline__ float4 h4_to_f4(uint2 u) {
    __half2 a = *reinterpret_cast<__half2*>(&u.x);
    __half2 b = *reinterpret_cast<__half2*>(&u.y);
    float2 fa = __half22float2(a), fb = __half22float2(b);
    return make_float4(fa.x, fa.y, fb.x, fb.y);
}

// z = h + sum neighbors (h fp16, fp32 accumulate), emitted as single fp16.
// 8 nodes per 256-thread block; unroll-2 gather (proven schedule).
__global__ void k_agg(const __half* __restrict__ h, const int* __restrict__ rowptr,
                      const int* __restrict__ col, __half* __restrict__ z16, int n) {
    int node = blockIdx.x * 8 + (threadIdx.x >> 5);
    if (node >= n) return;
    int lane = threadIdx.x & 31;                 // lane covers cols 4*lane..4*lane+3
    const uint2* h2 = reinterpret_cast<const uint2*>(h);
    float4 acc = h4_to_f4(__ldg(&h2[(size_t)node * 32 + lane]));
    int s0 = rowptr[node], s1 = rowptr[node + 1];
    int j = s0;
    for (; j + 1 < s1; j += 2) {
        int c0 = __ldg(&col[j]), c1 = __ldg(&col[j + 1]);
        float4 v0 = h4_to_f4(__ldg(&h2[(size_t)c0 * 32 + lane]));
        float4 v1 = h4_to_f4(__ldg(&h2[(size_t)c1 * 32 + lane]));
        acc.x += v0.x + v1.x; acc.y += v0.y + v1.y;
        acc.z += v0.z + v1.z; acc.w += v0.w + v1.w;
    }
    if (j < s1) {
        int c = __ldg(&col[j]);
        float4 v = h4_to_f4(__ldg(&h2[(size_t)c * 32 + lane]));
        acc.x += v.x; acc.y += v.y; acc.z += v.z; acc.w += v.w;
    }
    __half2 p0 = __floats2half2_rn(acc.x, acc.y);
    __half2 p1 = __floats2half2_rn(acc.z, acc.w);
    uint2 o;
    o.x = *reinterpret_cast<uint32_t*>(&p0);
    o.y = *reinterpret_cast<uint32_t*>(&p1);
    reinterpret_cast<uint2*>(z16)[(size_t)node * 32 + lane] = o;
}

// ---------------- fused 2-GEMM layer: h = relu(relu(z@Wa+ba)@Wb+bb) -----------
// Block tile 128x128; 8 warps (4m x 2n), warp tile 32x64; K=128.
// fp16 MMA, 2 terms: Z(fp16) @ (Whi + Wlo). SMEM fp16 row stride 272 B.
#define TSTR   272
#define SM_Z    0
#define SM_WAHI (128 * TSTR)                 // 34816
#define SM_WALO (2 * 128 * TSTR)             // 69632
#define SM_WBHI (3 * 128 * TSTR)             // 104448
#define SM_WBLO (4 * 128 * TSTR)             // 139264
#define SM_BA   (5 * 128 * TSTR)             // 174080
#define SM_BB   (SM_BA + 512)                // 174592
#define SMEM_L  (SM_BB + 512)                // 175104

__device__ __forceinline__ uint32_t smem_u32(const void* p) {
    uint32_t a;
    asm("{ .reg .u64 t; cvta.to.shared.u64 t, %1; cvt.u32.u64 %0, t; }" : "=r"(a) : "l"(p));
    return a;
}
__device__ __forceinline__ void ldsm_x4(uint32_t* r, uint32_t addr) {
    asm volatile("ldmatrix.sync.aligned.m8n8.x4.shared.b16 {%0,%1,%2,%3}, [%4];"
        : "=r"(r[0]), "=r"(r[1]), "=r"(r[2]), "=r"(r[3]) : "r"(addr));
}
__device__ __forceinline__ void mma_f16(float* c, const uint32_t* a, const uint32_t* b) {
    asm volatile(
        "mma.sync.aligned.m16n8k16.row.col.f32.f16.f16.f32 "
        "{%0,%1,%2,%3}, {%4,%5,%6,%7}, {%8,%9}, {%0,%1,%2,%3};"
        : "+f"(c[0]), "+f"(c[1]), "+f"(c[2]), "+f"(c[3])
        : "r"(a[0]), "r"(a[1]), "r"(a[2]), "r"(a[3]), "r"(b[0]), "r"(b[1]));
}
__device__ __forceinline__ void cp_async16(uint32_t saddr, const void* gptr) {
    asm volatile("cp.async.ca.shared.global [%0], [%1], 16;" :: "r"(saddr), "l"(gptr));
}
__device__ __forceinline__ uint32_t pack_half2(float a, float b) {
    __half2 t = __floats2half2_rn(a, b);
    return *reinterpret_cast<uint32_t*>(&t);
}

// One GEMM pass: acc = Z @ (Whi + Wlo), 2 fp16 MMA terms per B frag.
__device__ __forceinline__ void gemm_pass(uint32_t sb, uint32_t whi_ofs, uint32_t wlo_ofs,
                                          int lane, int m0, int n0, float acc[2][8][4]) {
#pragma unroll
    for (int a = 0; a < 2; a++)
#pragma unroll
        for (int b = 0; b < 8; b++)
#pragma unroll
            for (int c = 0; c < 4; c++) acc[a][b][c] = 0.f;

    const uint32_t a_row  = m0 + (lane & 15);
    const uint32_t a_coff = (lane >> 4) * 8;
    const uint32_t b_row  = n0 + ((lane >> 4) << 3) + (lane & 7);
    const uint32_t b_coff = ((lane >> 3) & 1) * 8;

#pragma unroll
    for (int ks = 0; ks < 8; ks++) {
        const int k = ks * 16;
        uint32_t ah[2][4];
#pragma unroll
        for (int mf = 0; mf < 2; mf++) {
            uint32_t addr = sb + SM_Z + (a_row + mf * 16) * TSTR + (k + a_coff) * 2;
            ldsm_x4(ah[mf], addr);
        }
#pragma unroll
        for (int nfg = 0; nfg < 4; nfg++) {
            uint32_t baddr = sb + whi_ofs + (b_row + nfg * 16) * TSTR + (k + b_coff) * 2;
            uint32_t bh[4], bl[4];
            ldsm_x4(bh, baddr);
            ldsm_x4(bl, baddr + (wlo_ofs - whi_ofs));
#pragma unroll
            for (int mf = 0; mf < 2; mf++) {
                mma_f16(acc[mf][nfg * 2 + 0], ah[mf], bh + 0);
                mma_f16(acc[mf][nfg * 2 + 0], ah[mf], bl + 0);
                mma_f16(acc[mf][nfg * 2 + 1], ah[mf], bh + 2);
                mma_f16(acc[mf][nfg * 2 + 1], ah[mf], bl + 2);
            }
        }
    }
}

__global__ __launch_bounds__(256, 1)
void k_layer(const uint4* __restrict__ Z16,
             const uint4* __restrict__ WaHi, const uint4* __restrict__ WaLo,
             const uint4* __restrict__ WbHi, const uint4* __restrict__ WbLo,
             const float* __restrict__ ba, const float* __restrict__ bb,
             __half* __restrict__ C16, int n) {
    extern __shared__ char sm[];
    const uint32_t sb = smem_u32(sm);
    const int tid = threadIdx.x;
    const int lane = tid & 31, w = tid >> 5;
    const int rowBase = blockIdx.x * 128;

    // ---- group 0: Z tile + Wa hi/lo (phase-1 inputs) ----
#pragma unroll
    for (int it = 0; it < 8; it++) {
        int j = tid + it * 256;              // 0..2047
        int row = j >> 4, chunk = j & 15;
        uint32_t dofs = row * TSTR + chunk * 16;
        cp_async16(sb + SM_Z + dofs, Z16 + (size_t)(rowBase + row) * 16 + chunk);
        cp_async16(sb + SM_WAHI + dofs, WaHi + row * 16 + chunk);
        cp_async16(sb + SM_WALO + dofs, WaLo + row * 16 + chunk);
    }
    asm volatile("cp.async.commit_group;" ::: "memory");

    // ---- group 1: Wb hi/lo (hidden under phase-1 compute) ----
#pragma unroll
    for (int it = 0; it < 8; it++) {
        int j = tid + it * 256;
        int row = j >> 4, chunk = j & 15;
        uint32_t dofs = row * TSTR + chunk * 16;
        cp_async16(sb + SM_WBHI + dofs, WbHi + row * 16 + chunk);
        cp_async16(sb + SM_WBLO + dofs, WbLo + row * 16 + chunk);
    }
    asm volatile("cp.async.commit_group;" ::: "memory");

    if (tid < 128) {
        reinterpret_cast<float*>(sm + SM_BA)[tid] = ba[tid];
        reinterpret_cast<float*>(sm + SM_BB)[tid] = bb[tid];
    }

    asm volatile("cp.async.wait_group 1;" ::: "memory");   // Z + Wa resident
    __syncthreads();

    const int m0 = (w >> 1) * 32, n0 = (w & 1) * 64;
    float acc[2][8][4];

    // ---- phase 1: acc1 = Z @ Wa ----
    gemm_pass(sb, SM_WAHI, SM_WALO, lane, m0, n0, acc);
    __syncthreads();                                       // all ldsm of Z done

    // ---- relu(acc1+ba) -> Z smem (single fp16), each warp its own quadrant ----
    {
        const float* bav = reinterpret_cast<const float*>(sm + SM_BA);
#pragma unroll
        for (int mf = 0; mf < 2; mf++) {
#pragma unroll
            for (int nf = 0; nf < 8; nf++) {
                int r = m0 + mf * 16 + (lane >> 2);
                int c = n0 + nf * 8 + (lane & 3) * 2;
                float b0 = bav[c], b1 = bav[c + 1];
                *reinterpret_cast<uint32_t*>(sm + SM_Z + r * TSTR + c * 2) =
                    pack_half2(fmaxf(acc[mf][nf][0] + b0, 0.f),
                               fmaxf(acc[mf][nf][1] + b1, 0.f));
                *reinterpret_cast<uint32_t*>(sm + SM_Z + (r + 8) * TSTR + c * 2) =
                    pack_half2(fmaxf(acc[mf][nf][2] + b0, 0.f),
                               fmaxf(acc[mf][nf][3] + b1, 0.f));
            }
        }
    }
    asm volatile("cp.async.wait_group 0;" ::: "memory");   // Wb resident
    __syncthreads();

    // ---- phase 2: acc2 = Z' @ Wb ----
    gemm_pass(sb, SM_WBHI, SM_WBLO, lane, m0, n0, acc);

    // ---- epilogue: relu(acc2+bb) -> global fp16 ----
    {
        const float* bbv = reinterpret_cast<const float*>(sm + SM_BB);
#pragma unroll
        for (int mf = 0; mf < 2; mf++) {
#pragma unroll
            for (int nf = 0; nf < 8; nf++) {
                int r = m0 + mf * 16 + (lane >> 2);
                int c = n0 + nf * 8 + (lane & 3) * 2;
                float b0 = bbv[c], b1 = bbv[c + 1];
                int gr0 = rowBase + r;
                if (gr0 < n) {
                    __half2 v = __floats2half2_rn(fmaxf(acc[mf][nf][0] + b0, 0.f),
                                                  fmaxf(acc[mf][nf][1] + b1, 0.f));
                    *reinterpret_cast<__half2*>(C16 + (size_t)gr0 * 128 + c) = v;
                }
                int gr1 = gr0 + 8;
                if (gr1 < n) {
                    __half2 v = __floats2half2_rn(fmaxf(acc[mf][nf][2] + b0, 0.f),
                                                  fmaxf(acc[mf][nf][3] + b1, 0.f));
                    *reinterpret_cast<__half2*>(C16 + (size_t)gr1 * 128 + c) = v;
                }
            }
        }
    }
}

// ---------------- pool + final -------------------------------------------------
__global__ void k_pool_partial(const __half* __restrict__ h, float* __restrict__ part, int n) {
    int d = threadIdx.x;
    float acc = 0.f;
    for (int r = blockIdx.x; r < n; r += gridDim.x)
        acc += __half2float(__ldg(&h[(size_t)r * D + d]));
    part[blockIdx.x * D + d] = acc;
}

__global__ void k_final(const float* __restrict__ part, const float* __restrict__ Wlin,
                        const float* __restrict__ blin, float* __restrict__ out) {
    __shared__ float pooled[D];
    int t = threadIdx.x;
    float acc = 0.f;
    for (int p = 0; p < NPART; p++) acc += part[p * D + t];
    pooled[t] = acc;
    __syncthreads();
    float o = blin[t];
    for (int d = 0; d < D; d++) o = fmaf(pooled[d], Wlin[d * D + t], o);
    out[t] = o;
}

// ---------------- launch -------------------------------------------------------
extern "C" void kernel_launch(void* const* d_in, const int* in_sizes, int n_in,
                              void* d_out, int out_size) {
    const int*   x    = (const int*)d_in[0];
    const int*   ei   = (const int*)d_in[1];
    const float* emb  = (const float*)d_in[2];
    const float* Wa   = (const float*)d_in[3];
    const float* ba   = (const float*)d_in[4];
    const float* Wb   = (const float*)d_in[5];
    const float* bb   = (const float*)d_in[6];
    const float* Wlin = (const float*)d_in[7];
    const float* blin = (const float*)d_in[8];
    float* out = (float*)d_out;

    const int N = in_sizes[0];
    const int E = in_sizes[1] / 2;
    const int* src = ei;
    const int* dst = ei + E;

    float *part;
    __half *h16, *z16;
    int *deg, *rowptr, *cursor, *col, *bsum, *boff;
    uint4 *whi, *wlo;
    cudaGetSymbolAddress((void**)&h16, g_h16);
    cudaGetSymbolAddress((void**)&z16, g_z16);
    cudaGetSymbolAddress((void**)&deg, g_deg);
    cudaGetSymbolAddress((void**)&rowptr, g_rowptr);
    cudaGetSymbolAddress((void**)&cursor, g_cursor);
    cudaGetSymbolAddress((void**)&col, g_col);
    cudaGetSymbolAddress((void**)&part, g_part);
    cudaGetSymbolAddress((void**)&bsum, g_bsum);
    cudaGetSymbolAddress((void**)&boff, g_boff);
    cudaGetSymbolAddress((void**)&whi, g_WhiT);
    cudaGetSymbolAddress((void**)&wlo, g_WloT);

    cudaFuncSetAttribute(k_layer, cudaFuncAttributeMaxDynamicSharedMemorySize, SMEM_L);

    // h = fp16(emb[x])
    k_gather<<<(N * 16 + 255) / 256, 256>>>(x, emb, h16, N);

    // pre-split weights to transposed fp16 hi/lo
    k_wsplit<<<40, 128>>>(Wa, Wb, (__half*)whi, (__half*)wlo);

    // CSR build
    k_zero_int<<<(N + 255) / 256, 256>>>(deg, N);
    k_count<<<(E + 255) / 256, 256>>>(dst, deg, E);
    const int nb = (N + SCAN_BLK - 1) / SCAN_BLK;
    k_scan_blk<<<nb, SCAN_BLK>>>(deg, rowptr, bsum, N);
    k_scan_top<<<1, 128>>>(bsum, boff, rowptr + N, nb);
    k_scan_add<<<(N + 255) / 256, 256>>>(rowptr, cursor, boff, N);
    k_scatter<<<(E + 255) / 256, 256>>>(src, dst, cursor, col, E);

    const int layer_blocks = (N + 127) / 128;
    const int agg_blocks   = (N + 7) / 8;
    for (int l = 0; l < L_LAYERS; l++) {
        // z = h + agg(h), fp32 accumulate, emitted as single fp16
        k_agg<<<agg_blocks, 256>>>(h16, rowptr, col, z16, N);
        // h = fp16(relu(relu(z@Wa+ba)@Wb+bb))
        k_layer<<<layer_blocks, 256, SMEM_L>>>(
            (const uint4*)z16,
            whi + (size_t)l * 2048, wlo + (size_t)l * 2048,
            whi + (size_t)(5 + l) * 2048, wlo + (size_t)(5 + l) * 2048,
            ba + l * D, bb + l * D, h16, N);
    }

    k_pool_partial<<<NPART, 128>>>(h16, part, N);
    k_final<<<1, 128>>>(part, Wlin, blin, out);
}